// round 7
// baseline (speedup 1.0000x reference)
#include <cuda_runtime.h>
#include <cuda_bf16.h>
#include <math.h>
#include <stdint.h>

#define BB 16
#define SS 512
#define DD 1024
#define NTOK (BB*SS)
#define NEG_BIG (-3.0e38f)
#define NPID 64
#define BK 32
#define NCH (DD / BK)
#define STR 40            // smem row stride in bf16 elems (80B)

// ------------------------------ scratch (static device globals; no allocs) --
__device__ uint16_t g_Eh[(size_t)NTOK * DD];
__device__ uint16_t g_El[(size_t)NTOK * DD];
__device__ uint16_t g_qh[(size_t)NTOK * DD];
__device__ uint16_t g_ql[(size_t)NTOK * DD];
__device__ uint16_t g_kh[(size_t)NTOK * DD];
__device__ uint16_t g_kl[(size_t)NTOK * DD];
__device__ uint16_t g_Wh[2][(size_t)DD * DD];
__device__ uint16_t g_Wl[2][(size_t)DD * DD];
__device__ float g_invn[NTOK];
__device__ int   g_idx0[NTOK];
__device__ int   g_idx1[NTOK];
__device__ int   g_cnt[2 * BB];
__device__ float g_pm[BB * NPID];
__device__ float g_pl[BB * NPID];
__device__ float g_pa[BB * NPID];

__device__ __forceinline__ void softmax_merge(float& m1, float& l1, float& a1,
                                              float m2, float l2, float a2) {
    float M  = fmaxf(m1, m2);
    float e1 = (l1 > 0.f) ? expf(m1 - M) : 0.f;
    float e2 = (l2 > 0.f) ? expf(m2 - M) : 0.f;
    l1 = l1 * e1 + l2 * e2;
    a1 = a1 * e1 + a2 * e2;
    m1 = M;
}

__device__ __forceinline__ uint32_t pack_bf2(float x, float y) {
    __nv_bfloat162 h = __floats2bfloat162_rn(x, y);
    return *(uint32_t*)&h;
}
// hi/lo split of 4 floats -> two uint32x2 (hi pair, lo pair)
__device__ __forceinline__ void split4(float4 v, uint2& h, uint2& l) {
    uint32_t h01 = pack_bf2(v.x, v.y), h23 = pack_bf2(v.z, v.w);
    __nv_bfloat162 a01 = *(__nv_bfloat162*)&h01, a23 = *(__nv_bfloat162*)&h23;
    uint32_t l01 = pack_bf2(v.x - __bfloat162float(a01.x), v.y - __bfloat162float(a01.y));
    uint32_t l23 = pack_bf2(v.z - __bfloat162float(a23.x), v.w - __bfloat162float(a23.y));
    h = make_uint2(h01, h23);
    l = make_uint2(l01, l23);
}
__device__ __forceinline__ void mma16816(float* c, const uint32_t* a, const uint32_t* b) {
    asm volatile(
        "mma.sync.aligned.m16n8k16.row.col.f32.bf16.bf16.f32 "
        "{%0,%1,%2,%3}, {%4,%5,%6,%7}, {%8,%9}, {%0,%1,%2,%3};"
        : "+f"(c[0]), "+f"(c[1]), "+f"(c[2]), "+f"(c[3])
        : "r"(a[0]), "r"(a[1]), "r"(a[2]), "r"(a[3]), "r"(b[0]), "r"(b[1]));
}

// ---------------------------------------------------------- mask compaction --
__global__ void prep_masks(const int* __restrict__ am, const int* __restrict__ tt) {
    int b = blockIdx.x;
    int t = threadIdx.x;
    int lane = t & 31, w = t >> 5;
    int a  = am[b * SS + t];
    int ty = tt[b * SS + t];
    bool f0 = (a == 1) && (ty == 0);
    bool f1 = (a == 1) && (ty == 1);
    unsigned bal0 = __ballot_sync(0xffffffffu, f0);
    unsigned bal1 = __ballot_sync(0xffffffffu, f1);
    __shared__ int wc0[16], wc1[16], off0[16], off1[16];
    if (lane == 0) { wc0[w] = __popc(bal0); wc1[w] = __popc(bal1); }
    __syncthreads();
    if (t == 0) {
        int s0 = 0, s1 = 0;
        for (int i = 0; i < 16; i++) {
            off0[i] = s0; s0 += wc0[i];
            off1[i] = s1; s1 += wc1[i];
        }
        g_cnt[b] = s0; g_cnt[BB + b] = s1;
    }
    __syncthreads();
    if (f0) g_idx0[b * SS + off0[w] + __popc(bal0 & ((1u << lane) - 1u))] = t;
    if (f1) g_idx1[b * SS + off1[w] + __popc(bal1 & ((1u << lane) - 1u))] = t;
}

// ----------------------- E hi/lo split + row inv-norms (one warp per row) ----
__global__ __launch_bounds__(256) void esplit_norms(const float* __restrict__ E) {
    int row  = blockIdx.x * 8 + (threadIdx.x >> 5);
    int lane = threadIdx.x & 31;
    const float4* p = (const float4*)(E + (size_t)row * DD);
    uint2* eh = (uint2*)(g_Eh + (size_t)row * DD);
    uint2* el = (uint2*)(g_El + (size_t)row * DD);
    float s = 0.f;
    #pragma unroll
    for (int i = 0; i < 8; i++) {
        float4 v = p[lane + i * 32];
        s += v.x * v.x + v.y * v.y + v.z * v.z + v.w * v.w;
        uint2 h, l;
        split4(v, h, l);
        eh[lane + i * 32] = h;
        el[lane + i * 32] = l;
    }
    #pragma unroll
    for (int o = 16; o > 0; o >>= 1) s += __shfl_down_sync(0xffffffffu, s, o);
    if (lane == 0) g_invn[row] = 1.f / fmaxf(sqrtf(s), 1e-12f);
}

// ------------------------------------------------------------ W hi/lo split --
__global__ __launch_bounds__(256) void wsplit(const float* __restrict__ Wq,
                                              const float* __restrict__ Wk) {
    int which = blockIdx.y;
    const float* W = which ? Wk : Wq;
    size_t i = (size_t)blockIdx.x * 256 + threadIdx.x;    // float4 index
    float4 v = ((const float4*)W)[i];
    uint2 h, l;
    split4(v, h, l);
    ((uint2*)g_Wh[which])[i] = h;
    ((uint2*)g_Wl[which])[i] = l;
}

// ---------------- bf16x3 gathered projection GEMM (pre-split operands) ------
// 64 x 128 tiles; writes q/k directly as hi/lo bf16 splits.
__global__ __launch_bounds__(256) void proj_mma(
    const float* __restrict__ bq, const float* __restrict__ bk)
{
    int z = blockIdx.z;
    int b = z & 15, which = z >> 4;
    int nr = g_cnt[which * BB + b];
    int r0 = blockIdx.y * 64;
    if (r0 >= nr) return;
    int c0 = blockIdx.x * 128;
    const float*    __restrict__ bias = which ? bk : bq;
    const int*      __restrict__ idx  = which ? g_idx1 : g_idx0;
    const uint16_t* __restrict__ Wh   = g_Wh[which];
    const uint16_t* __restrict__ Wl   = g_Wl[which];
    uint16_t* __restrict__ outh = which ? g_kh : g_qh;
    uint16_t* __restrict__ outl = which ? g_kl : g_ql;

    __shared__ __align__(16) uint16_t Ah[64 * STR];
    __shared__ __align__(16) uint16_t Al[64 * STR];
    __shared__ __align__(16) uint16_t Bh[128 * STR];
    __shared__ __align__(16) uint16_t Bl[128 * STR];
    __shared__ int sidx[64];

    int t = threadIdx.x;
    if (t < 64) sidx[t] = idx[b * SS + min(r0 + t, nr - 1)];
    __syncthreads();

    int row = t >> 2;           // 0..63
    int seg = t & 3;            // 0..3 (16B = 8 bf16 elems)
    // FIX: batch offset b*SS on the gathered E rows
    size_t arow = (size_t)b * SS + sidx[row];
    const uint16_t* ah_p = g_Eh + arow * DD + seg * 8;
    const uint16_t* al_p = g_El + arow * DD + seg * 8;
    const uint16_t* bh_p0 = Wh + (size_t)(c0 + row) * DD + seg * 8;
    const uint16_t* bl_p0 = Wl + (size_t)(c0 + row) * DD + seg * 8;
    const uint16_t* bh_p1 = Wh + (size_t)(c0 + row + 64) * DD + seg * 8;
    const uint16_t* bl_p1 = Wl + (size_t)(c0 + row + 64) * DD + seg * 8;

    int wid = t >> 5, lane = t & 31;
    int wy = wid >> 2, wx = wid & 3;
    int grp = lane >> 2, qd = lane & 3;

    float acc[2][4][4];
    #pragma unroll
    for (int mt = 0; mt < 2; mt++)
        #pragma unroll
        for (int nt = 0; nt < 4; nt++)
            #pragma unroll
            for (int r = 0; r < 4; r++) acc[mt][nt][r] = 0.f;

    uint4 rah = *(const uint4*)ah_p, ral = *(const uint4*)al_p;
    uint4 rbh0 = *(const uint4*)bh_p0, rbl0 = *(const uint4*)bl_p0;
    uint4 rbh1 = *(const uint4*)bh_p1, rbl1 = *(const uint4*)bl_p1;

    for (int c = 0; c < NCH; c++) {
        *(uint4*)(Ah + row * STR + seg * 8) = rah;
        *(uint4*)(Al + row * STR + seg * 8) = ral;
        *(uint4*)(Bh + row * STR + seg * 8) = rbh0;
        *(uint4*)(Bl + row * STR + seg * 8) = rbl0;
        *(uint4*)(Bh + (row + 64) * STR + seg * 8) = rbh1;
        *(uint4*)(Bl + (row + 64) * STR + seg * 8) = rbl1;
        __syncthreads();

        if (c < NCH - 1) {
            int k0 = (c + 1) * BK;
            rah = *(const uint4*)(ah_p + k0);
            ral = *(const uint4*)(al_p + k0);
            rbh0 = *(const uint4*)(bh_p0 + k0);
            rbl0 = *(const uint4*)(bl_p0 + k0);
            rbh1 = *(const uint4*)(bh_p1 + k0);
            rbl1 = *(const uint4*)(bl_p1 + k0);
        }

        #pragma unroll
        for (int ks = 0; ks < 2; ks++) {
            uint32_t bhf[4][2], blf[4][2];
            #pragma unroll
            for (int nt = 0; nt < 4; nt++) {
                int boff = (wx * 32 + nt * 8 + grp) * STR + qd * 2 + ks * 16;
                bhf[nt][0] = *(const uint32_t*)(Bh + boff);
                bhf[nt][1] = *(const uint32_t*)(Bh + boff + 8);
                blf[nt][0] = *(const uint32_t*)(Bl + boff);
                blf[nt][1] = *(const uint32_t*)(Bl + boff + 8);
            }
            #pragma unroll
            for (int mt = 0; mt < 2; mt++) {
                int aoff = (wy * 32 + mt * 16 + grp) * STR + qd * 2 + ks * 16;
                uint32_t ahf[4], alf[4];
                ahf[0] = *(const uint32_t*)(Ah + aoff);
                ahf[1] = *(const uint32_t*)(Ah + aoff + 8 * STR);
                ahf[2] = *(const uint32_t*)(Ah + aoff + 8);
                ahf[3] = *(const uint32_t*)(Ah + aoff + 8 * STR + 8);
                alf[0] = *(const uint32_t*)(Al + aoff);
                alf[1] = *(const uint32_t*)(Al + aoff + 8 * STR);
                alf[2] = *(const uint32_t*)(Al + aoff + 8);
                alf[3] = *(const uint32_t*)(Al + aoff + 8 * STR + 8);
                #pragma unroll
                for (int nt = 0; nt < 4; nt++) {
                    mma16816(acc[mt][nt], ahf, bhf[nt]);
                    mma16816(acc[mt][nt], ahf, blf[nt]);
                    mma16816(acc[mt][nt], alf, bhf[nt]);
                }
            }
        }
        __syncthreads();
    }

    // epilogue: bias + hi/lo split store of q/k
    #pragma unroll
    for (int mt = 0; mt < 2; mt++) {
        int rA = r0 + wy * 32 + mt * 16 + grp;
        #pragma unroll
        for (int nt = 0; nt < 4; nt++) {
            int col = c0 + wx * 32 + nt * 8 + qd * 2;
            float2 bv = *(const float2*)(bias + col);
            if (rA < nr) {
                float v0 = acc[mt][nt][0] + bv.x, v1 = acc[mt][nt][1] + bv.y;
                uint32_t h = pack_bf2(v0, v1);
                __nv_bfloat162 hh = *(__nv_bfloat162*)&h;
                uint32_t l = pack_bf2(v0 - __bfloat162float(hh.x), v1 - __bfloat162float(hh.y));
                size_t o = ((size_t)b * SS + rA) * DD + col;
                *(uint32_t*)(outh + o) = h;
                *(uint32_t*)(outl + o) = l;
            }
            if (rA + 8 < nr) {
                float v0 = acc[mt][nt][2] + bv.x, v1 = acc[mt][nt][3] + bv.y;
                uint32_t h = pack_bf2(v0, v1);
                __nv_bfloat162 hh = *(__nv_bfloat162*)&h;
                uint32_t l = pack_bf2(v0 - __bfloat162float(hh.x), v1 - __bfloat162float(hh.y));
                size_t o = ((size_t)b * SS + rA + 8) * DD + col;
                *(uint32_t*)(outh + o) = h;
                *(uint32_t*)(outl + o) = l;
            }
        }
    }
}

// --------- bf16x3 fused pair + online softmax (64x64 tiles, pre-split) ------
__global__ __launch_bounds__(256) void pair_mma() {
    int b   = blockIdx.z;
    int pid = blockIdx.y * 8 + blockIdx.x;
    int n0  = g_cnt[b], n1 = g_cnt[BB + b];
    int i0  = blockIdx.y * 64, j0 = blockIdx.x * 64;
    int tid = threadIdx.x;
    if (i0 >= n0 || j0 >= n1) {
        if (tid == 0) {
            g_pm[b * NPID + pid] = NEG_BIG;
            g_pl[b * NPID + pid] = 0.f;
            g_pa[b * NPID + pid] = 0.f;
        }
        return;
    }

    __shared__ __align__(16) uint16_t Qh[64 * STR], Ql[64 * STR];
    __shared__ __align__(16) uint16_t Ih[64 * STR], Il[64 * STR];
    __shared__ __align__(16) uint16_t Kh[64 * STR], Kl[64 * STR];
    __shared__ __align__(16) uint16_t Jh[64 * STR], Jl[64 * STR];
    __shared__ float sinvi[64], sinvj[64];
    __shared__ int   si[64], sj[64];

    if (tid < 64) {
        int r  = min(i0 + tid, n0 - 1);
        int ix = g_idx0[b * SS + r];
        si[tid] = ix; sinvi[tid] = g_invn[b * SS + ix];
        int c  = min(j0 + tid, n1 - 1);
        int jx = g_idx1[b * SS + c];
        sj[tid] = jx; sinvj[tid] = g_invn[b * SS + jx];
    }
    __syncthreads();

    int row = tid >> 2, seg = tid & 3;
    size_t qrow = (size_t)b * SS + min(i0 + row, n0 - 1);
    size_t krow = (size_t)b * SS + min(j0 + row, n1 - 1);
    size_t irow = (size_t)b * SS + si[row];
    size_t jrow = (size_t)b * SS + sj[row];
    const uint16_t* qh_p = g_qh + qrow * DD + seg * 8;
    const uint16_t* ql_p = g_ql + qrow * DD + seg * 8;
    const uint16_t* ih_p = g_Eh + irow * DD + seg * 8;
    const uint16_t* il_p = g_El + irow * DD + seg * 8;
    const uint16_t* kh_p = g_kh + krow * DD + seg * 8;
    const uint16_t* kl_p = g_kl + krow * DD + seg * 8;
    const uint16_t* jh_p = g_Eh + jrow * DD + seg * 8;
    const uint16_t* jl_p = g_El + jrow * DD + seg * 8;

    int wid = tid >> 5, lane = tid & 31;
    int wy = wid >> 2, wx = wid & 3;
    int grp = lane >> 2, qd = lane & 3;

    float aL[2][2][4], aG[2][2][4];
    #pragma unroll
    for (int mt = 0; mt < 2; mt++)
        #pragma unroll
        for (int nt = 0; nt < 2; nt++)
            #pragma unroll
            for (int r = 0; r < 4; r++) { aL[mt][nt][r] = 0.f; aG[mt][nt][r] = 0.f; }

    uint4 rq = *(const uint4*)qh_p, rql = *(const uint4*)ql_p;
    uint4 ri = *(const uint4*)ih_p, ril = *(const uint4*)il_p;
    uint4 rk = *(const uint4*)kh_p, rkl = *(const uint4*)kl_p;
    uint4 rj = *(const uint4*)jh_p, rjl = *(const uint4*)jl_p;

    for (int c = 0; c < NCH; c++) {
        *(uint4*)(Qh + row * STR + seg * 8) = rq;
        *(uint4*)(Ql + row * STR + seg * 8) = rql;
        *(uint4*)(Ih + row * STR + seg * 8) = ri;
        *(uint4*)(Il + row * STR + seg * 8) = ril;
        *(uint4*)(Kh + row * STR + seg * 8) = rk;
        *(uint4*)(Kl + row * STR + seg * 8) = rkl;
        *(uint4*)(Jh + row * STR + seg * 8) = rj;
        *(uint4*)(Jl + row * STR + seg * 8) = rjl;
        __syncthreads();

        if (c < NCH - 1) {
            int k0 = (c + 1) * BK;
            rq  = *(const uint4*)(qh_p + k0);
            rql = *(const uint4*)(ql_p + k0);
            ri  = *(const uint4*)(ih_p + k0);
            ril = *(const uint4*)(il_p + k0);
            rk  = *(const uint4*)(kh_p + k0);
            rkl = *(const uint4*)(kl_p + k0);
            rj  = *(const uint4*)(jh_p + k0);
            rjl = *(const uint4*)(jl_p + k0);
        }

        #pragma unroll
        for (int ks = 0; ks < 2; ks++) {
            uint32_t kbh[2][2], kbl[2][2], jbh[2][2], jbl[2][2];
            #pragma unroll
            for (int nt = 0; nt < 2; nt++) {
                int boff = (wx * 16 + nt * 8 + grp) * STR + qd * 2 + ks * 16;
                kbh[nt][0] = *(const uint32_t*)(Kh + boff);
                kbh[nt][1] = *(const uint32_t*)(Kh + boff + 8);
                kbl[nt][0] = *(const uint32_t*)(Kl + boff);
                kbl[nt][1] = *(const uint32_t*)(Kl + boff + 8);
                jbh[nt][0] = *(const uint32_t*)(Jh + boff);
                jbh[nt][1] = *(const uint32_t*)(Jh + boff + 8);
                jbl[nt][0] = *(const uint32_t*)(Jl + boff);
                jbl[nt][1] = *(const uint32_t*)(Jl + boff + 8);
            }
            #pragma unroll
            for (int mt = 0; mt < 2; mt++) {
                int aoff = (wy * 32 + mt * 16 + grp) * STR + qd * 2 + ks * 16;
                uint32_t qah[4], qal[4], iah[4], ial[4];
                qah[0] = *(const uint32_t*)(Qh + aoff);
                qah[1] = *(const uint32_t*)(Qh + aoff + 8 * STR);
                qah[2] = *(const uint32_t*)(Qh + aoff + 8);
                qah[3] = *(const uint32_t*)(Qh + aoff + 8 * STR + 8);
                qal[0] = *(const uint32_t*)(Ql + aoff);
                qal[1] = *(const uint32_t*)(Ql + aoff + 8 * STR);
                qal[2] = *(const uint32_t*)(Ql + aoff + 8);
                qal[3] = *(const uint32_t*)(Ql + aoff + 8 * STR + 8);
                iah[0] = *(const uint32_t*)(Ih + aoff);
                iah[1] = *(const uint32_t*)(Ih + aoff + 8 * STR);
                iah[2] = *(const uint32_t*)(Ih + aoff + 8);
                iah[3] = *(const uint32_t*)(Ih + aoff + 8 * STR + 8);
                ial[0] = *(const uint32_t*)(Il + aoff);
                ial[1] = *(const uint32_t*)(Il + aoff + 8 * STR);
                ial[2] = *(const uint32_t*)(Il + aoff + 8);
                ial[3] = *(const uint32_t*)(Il + aoff + 8 * STR + 8);
                #pragma unroll
                for (int nt = 0; nt < 2; nt++) {
                    mma16816(aL[mt][nt], qah, kbh[nt]);
                    mma16816(aL[mt][nt], qah, kbl[nt]);
                    mma16816(aL[mt][nt], qal, kbh[nt]);
                    mma16816(aG[mt][nt], iah, jbh[nt]);
                    mma16816(aG[mt][nt], iah, jbl[nt]);
                    mma16816(aG[mt][nt], ial, jbh[nt]);
                }
            }
        }
        __syncthreads();
    }

    // epilogue: per-thread online softmax over its 16 pairs
    float m = NEG_BIG, l = 0.f, a = 0.f;
    #pragma unroll
    for (int mt = 0; mt < 2; mt++)
        #pragma unroll
        for (int nt = 0; nt < 2; nt++)
            #pragma unroll
            for (int rr = 0; rr < 2; rr++)
                #pragma unroll
                for (int cc = 0; cc < 2; cc++) {
                    int li = wy * 32 + mt * 16 + grp + rr * 8;
                    int lj = wx * 16 + nt * 8 + qd * 2 + cc;
                    if (i0 + li < n0 && j0 + lj < n1)
                        m = fmaxf(m, aL[mt][nt][rr * 2 + cc]);
                }
    if (m > NEG_BIG * 0.5f) {
        #pragma unroll
        for (int mt = 0; mt < 2; mt++)
            #pragma unroll
            for (int nt = 0; nt < 2; nt++)
                #pragma unroll
                for (int rr = 0; rr < 2; rr++)
                    #pragma unroll
                    for (int cc = 0; cc < 2; cc++) {
                        int li = wy * 32 + mt * 16 + grp + rr * 8;
                        int lj = wx * 16 + nt * 8 + qd * 2 + cc;
                        if (i0 + li < n0 && j0 + lj < n1) {
                            float w  = expf(aL[mt][nt][rr * 2 + cc] - m);
                            float sc = fabsf(aG[mt][nt][rr * 2 + cc]) * sinvi[li] * sinvj[lj];
                            l += w;
                            a += w * sc;
                        }
                    }
    }

    __shared__ float rm_[256], rl_[256], ra_[256];
    rm_[tid] = m; rl_[tid] = l; ra_[tid] = a;
    __syncthreads();
    for (int s = 128; s > 0; s >>= 1) {
        if (tid < s) {
            float M = rm_[tid], L = rl_[tid], A = ra_[tid];
            softmax_merge(M, L, A, rm_[tid + s], rl_[tid + s], ra_[tid + s]);
            rm_[tid] = M; rl_[tid] = L; ra_[tid] = A;
        }
        __syncthreads();
    }
    if (tid == 0) {
        g_pm[b * NPID + pid] = rm_[0];
        g_pl[b * NPID + pid] = rl_[0];
        g_pa[b * NPID + pid] = ra_[0];
    }
}

// ------------------------------------------------------------------ finalize --
__global__ void finalize(float* __restrict__ out) {
    int b = blockIdx.x;
    int t = threadIdx.x;   // 64 threads
    __shared__ float sm[64], sl[64], sa[64];
    sm[t] = g_pm[b * NPID + t];
    sl[t] = g_pl[b * NPID + t];
    sa[t] = g_pa[b * NPID + t];
    __syncthreads();
    for (int s = 32; s > 0; s >>= 1) {
        if (t < s) {
            float M = sm[t], L = sl[t], A = sa[t];
            softmax_merge(M, L, A, sm[t + s], sl[t + s], sa[t + s]);
            sm[t] = M; sl[t] = L; sa[t] = A;
        }
        __syncthreads();
    }
    if (t == 0) out[b] = (sl[0] > 0.f) ? (sa[0] / sl[0]) : 0.f;
}

// -------------------------------------------------------------------- launch --
extern "C" void kernel_launch(void* const* d_in, const int* in_sizes, int n_in,
                              void* d_out, int out_size) {
    const float* E  = (const float*)d_in[0];
    const float* Wq = (const float*)d_in[1];
    const float* bq = (const float*)d_in[2];
    const float* Wk = (const float*)d_in[3];
    const float* bk = (const float*)d_in[4];
    const int*   am = (const int*)d_in[5];
    const int*   tt = (const int*)d_in[6];
    float* out = (float*)d_out;

    prep_masks<<<BB, 512>>>(am, tt);
    esplit_norms<<<NTOK / 8, 256>>>(E);
    wsplit<<<dim3(DD * DD / 4 / 256, 2), 256>>>(Wq, Wk);
    proj_mma<<<dim3(8, 8, 2 * BB), 256>>>(bq, bk);
    pair_mma<<<dim3(8, 8, BB), 256>>>();
    finalize<<<BB, 64>>>(out);
}